// round 6
// baseline (speedup 1.0000x reference)
#include <cuda_runtime.h>

// Per-channel 5x5 correlation, stride=1, pad=2; 128 planes of 512x512 f32.
// Register-rolling, 4 warps/CTA, warp owns a 256-wide x 16-row strip.
//   - lane owns 8 x; loads its OWN halo: LDG.64(x0-2) + 2x LDG.128 + LDG.64(x0+8)
//     (halo lines are L1/L2 resident from neighbor lanes -> no extra DRAM).
//     No shuffles, no edge-lane special cases.
//   - depth-2 row prefetch (double-buffered raw regs, parity compile-time).
//   - 5 pending output rows in registers, mod-5 rotation; slot's FIRST tap is
//     mul.f32x2 (no acc zeroing), completed row stored as ulonglong2 (no upk).
//   - packed f32x2 FMA: 100 FMA2/MUL2 per row-step (8 outputs wide).

#define IMG  512
#define R    16
#define NSTEP (R + 4)      // 20 input rows per strip

__device__ __forceinline__ unsigned long long pk(float lo, float hi) {
    unsigned long long r;
    asm("mov.b64 %0, {%1, %2};" : "=l"(r) : "f"(lo), "f"(hi));
    return r;
}
__device__ __forceinline__ unsigned long long fma2(unsigned long long a,
                                                   unsigned long long b,
                                                   unsigned long long c) {
    unsigned long long d;
    asm("fma.rn.f32x2 %0, %1, %2, %3;" : "=l"(d) : "l"(a), "l"(b), "l"(c));
    return d;
}
__device__ __forceinline__ unsigned long long mul2(unsigned long long a,
                                                   unsigned long long b) {
    unsigned long long d;
    asm("mul.rn.f32x2 %0, %1, %2;" : "=l"(d) : "l"(a), "l"(b));
    return d;
}

// All 25 taps of input-row (s) into the 5 pending output slots. I = s mod 5.
// kr==0 hits the slot that was just stored: first tap overwrites (mul).
template<int I>
__device__ __forceinline__ void accstep(unsigned long long acc[5][4],
                                        const unsigned long long* __restrict__ wp,
                                        const unsigned long long* __restrict__ p) {
    #pragma unroll
    for (int kr = 0; kr < 5; kr++) {
        const int slot = ((I - kr) % 5 + 5) % 5;
        #pragma unroll
        for (int t = 0; t < 5; t++) {
            #pragma unroll
            for (int pj = 0; pj < 4; pj++) {
                if (kr == 0 && t == 0)
                    acc[slot][pj] = mul2(wp[0], p[2 * pj]);
                else
                    acc[slot][pj] = fma2(wp[kr * 5 + t], p[2 * pj + t], acc[slot][pj]);
            }
        }
    }
}

__global__ __launch_bounds__(128, 5) void conv5x5_kernel(
    const float* __restrict__ X,
    const float* __restrict__ Kw,
    float* __restrict__ Out)
{
    const int lane  = threadIdx.x;
    const int wrp   = threadIdx.y;                  // 0..3
    const int c     = blockIdx.z;
    const int warpX = blockIdx.x;                   // 0..1
    const int strip = blockIdx.y * 4 + wrp;         // 0..31
    const int Y0    = strip * R;
    const int x0    = warpX * 256 + lane * 8;

    const bool hasL = (x0 >= 2);            // false only for x0 == 0
    const bool hasR = (x0 + 9 < IMG);       // false only for x0 == 504

    const float* __restrict__ Xc = X   + (size_t)c * (IMG * IMG);
    float*       __restrict__ Oc = Out + (size_t)c * (IMG * IMG);

    // packed (w,w) weights (warp-uniform -> UR promotion)
    unsigned long long wp[25];
    #pragma unroll
    for (int i = 0; i < 25; i++) { const float wv = __ldg(&Kw[i]); wp[i] = pk(wv, wv); }

    unsigned long long acc[5][4];
    #pragma unroll
    for (int j = 0; j < 5; j++)
        #pragma unroll
        for (int q = 0; q < 4; q++) acc[j][q] = 0ull;   // one-time; rotation uses mul

    unsigned long long p[11];
    float2 H0b[2], H1b[2];      // halo pairs  v[-2,-1] and v[8,9]
    float4 Ab[2],  Bb[2];       // own 8 floats v[0..7]

// Load input row for step S into buffer PAR (zero outside image / past strip).
#define LOADROW(S, PAR) do {                                                   \
    const int s__ = (S);                                                       \
    const int gy_ = Y0 - 2 + s__;                                              \
    H0b[PAR] = make_float2(0.f, 0.f); H1b[PAR] = make_float2(0.f, 0.f);        \
    Ab[PAR]  = make_float4(0.f,0.f,0.f,0.f);                                   \
    Bb[PAR]  = make_float4(0.f,0.f,0.f,0.f);                                   \
    if (s__ < NSTEP && (unsigned)gy_ < (unsigned)IMG) {                        \
        const float* rp_ = Xc + (size_t)gy_ * IMG + x0;                        \
        Ab[PAR] = *reinterpret_cast<const float4*>(rp_);                       \
        Bb[PAR] = *reinterpret_cast<const float4*>(rp_ + 4);                   \
        if (hasL) H0b[PAR] = *reinterpret_cast<const float2*>(rp_ - 2);        \
        if (hasR) H1b[PAR] = *reinterpret_cast<const float2*>(rp_ + 8);        \
    }                                                                          \
} while (0)

// Pack buffer PAR into p[0..10]; even pairs are adjacent members (coalesced).
#define PACKROW(PAR) do {                                                      \
    p[0]  = pk(H0b[PAR].x, H0b[PAR].y);                                        \
    p[1]  = pk(H0b[PAR].y, Ab[PAR].x);                                         \
    p[2]  = pk(Ab[PAR].x,  Ab[PAR].y);                                         \
    p[3]  = pk(Ab[PAR].y,  Ab[PAR].z);                                         \
    p[4]  = pk(Ab[PAR].z,  Ab[PAR].w);                                         \
    p[5]  = pk(Ab[PAR].w,  Bb[PAR].x);                                         \
    p[6]  = pk(Bb[PAR].x,  Bb[PAR].y);                                         \
    p[7]  = pk(Bb[PAR].y,  Bb[PAR].z);                                         \
    p[8]  = pk(Bb[PAR].z,  Bb[PAR].w);                                         \
    p[9]  = pk(Bb[PAR].w,  H1b[PAR].x);                                        \
    p[10] = pk(H1b[PAR].x, H1b[PAR].y);                                        \
} while (0)

// Step s = sb + I: prefetch row s+2 into buf[s&1]; FMA row s (in p);
// store completed row s-4 (slot (I+1)%5) as ulonglong2; pack row s+1 into p.
#define STEP(I) do {                                                           \
    const int s_ = sb + (I);                                                   \
    LOADROW(s_ + 2, ((I) & 1));                                                \
    accstep<((I) % 5)>(acc, wp, p);                                            \
    if (s_ >= 4) {                                                             \
        float* op_ = Oc + (size_t)(Y0 + s_ - 4) * IMG + x0;                    \
        ulonglong2 o0_, o1_;                                                   \
        o0_.x = acc[((I)+1)%5][0]; o0_.y = acc[((I)+1)%5][1];                  \
        o1_.x = acc[((I)+1)%5][2]; o1_.y = acc[((I)+1)%5][3];                  \
        *reinterpret_cast<ulonglong2*>(op_)     = o0_;                         \
        *reinterpret_cast<ulonglong2*>(op_ + 4) = o1_;                         \
    }                                                                          \
    PACKROW(((I)+1) & 1);                                                      \
} while (0)

    // prologue: rows 0,1 into buffers; pack row 0
    LOADROW(0, 0);
    LOADROW(1, 1);
    PACKROW(0);

    // 20 steps in unroll-10 blocks (sb = 0, 10)
    #pragma unroll 1
    for (int sb = 0; sb < NSTEP; sb += 10) {
        STEP(0); STEP(1); STEP(2); STEP(3); STEP(4);
        STEP(5); STEP(6); STEP(7); STEP(8); STEP(9);
    }

#undef STEP
#undef PACKROW
#undef LOADROW
}

extern "C" void kernel_launch(void* const* d_in, const int* in_sizes, int n_in,
                              void* d_out, int out_size)
{
    const float* X  = (const float*)d_in[0];
    const float* Kw = (const float*)d_in[1];
    float* Out      = (float*)d_out;

    dim3 grid(2, IMG / R / 4, 128);   // 2 x-halves, 8 strip-groups, 128 planes = 2048 CTAs
    dim3 block(32, 4);                // 4 warps, each owns one 256x16 strip
    conv5x5_kernel<<<grid, block>>>(X, Kw, Out);
}